// round 14
// baseline (speedup 1.0000x reference)
#include <cuda_runtime.h>
#include <cuda_fp16.h>

// ---------------------------------------------------------------------------
// Problem constants
// ---------------------------------------------------------------------------
#define NN     2048
#define NSC    81
#define NB     64
#define TPB    256
#define WSZ    94
#define NOUT   (NN - WSZ + 1)  // 1955

#define S0F        0.1936026618f            // 2*dt*(w0+sqrt(2+w0^2))/(4*pi)
#define WFAC       0.030679615757712823f    // 2*pi / (2048*0.1)
#define KFAC       0.0030679615757712823f   // 2*pi / 2048
#define TWOPI_F    6.283185307179586f
#define INV_PI4    0.7511255444649425f      // pi^(-1/4)
#define RSQ2       0.70710678118654752f
#define LAMB       16.0f                    // fp16 range centering; cancels in ratio

// ---------------------------------------------------------------------------
// Packed complex type: one 64-bit reg pair holding (re, im) as f32x2
// ---------------------------------------------------------------------------
typedef unsigned long long c64;

__device__ __forceinline__ c64 PKc(float x, float y) {
    c64 r; asm("mov.b64 %0, {%1,%2};" : "=l"(r) : "f"(x), "f"(y)); return r;
}
__device__ __forceinline__ void UPKc(c64 v, float& x, float& y) {
    asm("mov.b64 {%0,%1}, %2;" : "=f"(x), "=f"(y) : "l"(v));
}
__device__ __forceinline__ c64 padd(c64 a, c64 b) {
    c64 r; asm("add.rn.f32x2 %0, %1, %2;" : "=l"(r) : "l"(a), "l"(b)); return r;
}
__device__ __forceinline__ c64 pmul(c64 a, c64 b) {
    c64 r; asm("mul.rn.f32x2 %0, %1, %2;" : "=l"(r) : "l"(a), "l"(b)); return r;
}
__device__ __forceinline__ c64 pfma(c64 a, c64 b, c64 c) {
    c64 r; asm("fma.rn.f32x2 %0, %1, %2, %3;" : "=l"(r) : "l"(a), "l"(b), "l"(c)); return r;
}
__device__ __forceinline__ c64 psub(c64 a, c64 b) { return pfma(b, PKc(-1.f, -1.f), a); }
__device__ __forceinline__ c64 pswap(c64 v) { float x, y; UPKc(v, x, y); return PKc(y, x); }

// a*b (4 fp instrs)
__device__ __forceinline__ c64 cmulc(c64 a, c64 b) {
    float ax, ay, bx, by; UPKc(a, ax, ay); UPKc(b, bx, by);
    return PKc(fmaf(ax, bx, -ay * by), fmaf(ax, by, ay * bx));
}
// a*conj(b) (4 fp instrs) — inverse twiddles without negation
__device__ __forceinline__ c64 cmulcj(c64 a, c64 b) {
    float ax, ay, bx, by; UPKc(a, ax, ay); UPKc(b, bx, by);
    return PKc(fmaf(ax, bx, ay * by), fmaf(ay, bx, -ax * by));
}
template <bool INV>
__device__ __forceinline__ c64 capply(c64 a, c64 w) {
    return INV ? cmulcj(a, w) : cmulc(a, w);
}

// ---------------------------------------------------------------------------
// Scratch (device globals; no allocation anywhere)
// ---------------------------------------------------------------------------
static __device__ c64     g_Y [NB * 2 * NN];
static __device__ __half2 g_Tp[(size_t)NB * NSC * NN];  // (T1, T2) fp16 pair
static __device__ __half2 g_Tc[(size_t)NB * NSC * NN];  // (T12.re, T12.im) fp16 pair
static __device__ float   g_coh[NB * NN];

// ---------------------------------------------------------------------------
// Data-buffer bank swizzle (conflict-free for all FFT patterns below)
// ---------------------------------------------------------------------------
__device__ __forceinline__ int gmask(int h) { return (h & 7) ^ ((h & 4) << 1); }
__device__ __forceinline__ int sw(int i)    { return i ^ gmask(i >> 4); }

// ---------------------------------------------------------------------------
// Twiddle tables (forward sign; INV uses a*conj(w)):
//   tw[k]           = exp(-i*pi*k/1024), k in [0,512)   (pass4 w1, linear reads)
//   ptw2[m*8+p]     = exp(-i*pi*m*p/32),  m in [0,8), p in [0,8)
//   ptw3[(m-1)*64+p]= exp(-i*pi*m*p/256), m in [1,8), p in [0,64)
// ---------------------------------------------------------------------------
__device__ __forceinline__ void fill_tables(c64* tw, c64* ptw2, c64* ptw3, int t) {
    #pragma unroll
    for (int k = t; k < 512; k += TPB) {
        float s, c;
        sincospif(-(float)k * (1.0f / 1024.0f), &s, &c);
        tw[k] = PKc(c, s);
    }
    if (t < 64) {
        int m = t >> 3, p = t & 7;
        float s, c;
        sincospif(-(float)(m * p) * (1.0f / 32.0f), &s, &c);
        ptw2[t] = PKc(c, s);
    }
    #pragma unroll
    for (int k = t; k < 448; k += TPB) {
        int m = 1 + (k >> 6), p = k & 63;
        float s, c;
        sincospif(-(float)(m * p) * (1.0f / 256.0f), &s, &c);
        ptw3[k] = PKc(c, s);
    }
}

// ---------------------------------------------------------------------------
// Packed radix-8 butterflies
// ---------------------------------------------------------------------------
template <bool INV>
__device__ __forceinline__ void bf8_tail(c64 E0, c64 E1, c64 E2, c64 E3,
                                         c64 O0, c64 O1, c64 O2, c64 O3,
                                         c64 v[8]) {
    const c64 CI1 = INV ? PKc(-1.f, 1.f) : PKc(1.f, -1.f);
    const c64 CI2 = INV ? PKc(1.f, -1.f) : PKc(-1.f, 1.f);
    const c64 PIM = PKc(-1.f, 1.f);
    c64 q1 = pfma(pswap(O1), PIM, O1);
    c64 q3 = pfma(pswap(O3), PIM, O3);
    c64 W1 = INV ? pmul(q1, PKc(RSQ2, RSQ2))
                 : pmul(pswap(q1), PKc(RSQ2, -RSQ2));
    c64 W3 = INV ? pmul(pswap(q3), PKc(-RSQ2, RSQ2))
                 : pmul(q3, PKc(-RSQ2, -RSQ2));
    c64 O2s = pswap(O2);
    v[0] = padd(E0, O0);        v[4] = psub(E0, O0);
    v[1] = padd(E1, W1);        v[5] = psub(E1, W1);
    v[2] = pfma(O2s, CI1, E2);  v[6] = pfma(O2s, CI2, E2);
    v[3] = padd(E3, W3);        v[7] = psub(E3, W3);
}

template <bool INV>
__device__ __forceinline__ void bf8(c64 v[8]) {
    const c64 CI1 = INV ? PKc(-1.f, 1.f) : PKc(1.f, -1.f);
    const c64 CI2 = INV ? PKc(1.f, -1.f) : PKc(-1.f, 1.f);
    c64 e0 = padd(v[0], v[4]), e1 = psub(v[0], v[4]);
    c64 e2 = padd(v[2], v[6]), e3 = psub(v[2], v[6]);
    c64 e3s = pswap(e3);
    c64 E0 = padd(e0, e2), E2 = psub(e0, e2);
    c64 E1 = pfma(e3s, CI1, e1), E3 = pfma(e3s, CI2, e1);
    c64 o0 = padd(v[1], v[5]), o1 = psub(v[1], v[5]);
    c64 o2 = padd(v[3], v[7]), o3 = psub(v[3], v[7]);
    c64 o3s = pswap(o3);
    c64 O0 = padd(o0, o2), O2 = psub(o0, o2);
    c64 O1 = pfma(o3s, CI1, o1), O3 = pfma(o3s, CI2, o1);
    bf8_tail<INV>(E0, E1, E2, E3, O0, O1, O2, O3, v);
}

// Half-input butterfly: v[0..3] valid, v[4..7] == 0 (Morlet filter support)
template <bool INV>
__device__ __forceinline__ void bf8h(c64 v[8]) {
    const c64 CI1 = INV ? PKc(-1.f, 1.f) : PKc(1.f, -1.f);
    const c64 CI2 = INV ? PKc(1.f, -1.f) : PKc(-1.f, 1.f);
    c64 a0 = v[0], a1 = v[2], b0 = v[1], b1 = v[3];
    c64 a1s = pswap(a1);
    c64 E0 = padd(a0, a1), E2 = psub(a0, a1);
    c64 E1 = pfma(a1s, CI1, a0), E3 = pfma(a1s, CI2, a0);
    c64 b1s = pswap(b1);
    c64 O0 = padd(b0, b1), O2 = psub(b0, b1);
    c64 O1 = pfma(b1s, CI1, b0), O3 = pfma(b1s, CI2, b0);
    bf8_tail<INV>(E0, E1, E2, E3, O0, O1, O2, O3, v);
}

// ---------------------------------------------------------------------------
// Stockham passes, N = 2048 = 8*8*8*4, 256 threads, PING-PONG buffers.
// Per FFT: pass1 -> P, pass2 P->Q, pass3 Q->P, pass4 reads P (regs out).
// One trailing __syncthreads per pass; pass4 has none (the next pass1's
// trailing sync orders pass4's reads before later writes).
// ---------------------------------------------------------------------------
template <bool INV, bool HALF>
__device__ __forceinline__ void pass1(c64* dst, c64 v[8], int t) {
    if (HALF) bf8h<INV>(v); else bf8<INV>(v);
    int mw = gmask(t >> 1);
    int b8 = 8 * t;
    #pragma unroll
    for (int r = 0; r < 8; r++) dst[(b8 + r) ^ mw] = v[r];
    __syncthreads();
}

template <bool INV>
__device__ __forceinline__ void pass2(const c64* src, c64* dst, const c64* ptw2, int t) {
    c64 v[8];
    int mr = gmask(t >> 4);
    #pragma unroll
    for (int m = 0; m < 8; m++) v[m] = src[(t + 256 * m) ^ mr];
    int p = t & 7;
    #pragma unroll
    for (int m = 1; m < 8; m++) v[m] = capply<INV>(v[m], ptw2[m * 8 + p]);
    bf8<INV>(v);
    int o = (t >> 3) * 64 + p;
    #pragma unroll
    for (int r = 0; r < 8; r++) { int i = o + 8 * r; dst[sw(i)] = v[r]; }
    __syncthreads();
}

template <bool INV>
__device__ __forceinline__ void pass3(const c64* src, c64* dst, const c64* ptw3, int t) {
    c64 v[8];
    int mr = gmask(t >> 4);
    #pragma unroll
    for (int m = 0; m < 8; m++) v[m] = src[(t + 256 * m) ^ mr];
    int p = t & 63;
    #pragma unroll
    for (int m = 1; m < 8; m++) v[m] = capply<INV>(v[m], ptw3[(m - 1) * 64 + p]);
    bf8<INV>(v);
    int o = (t >> 6) * 512 + p;
    #pragma unroll
    for (int r = 0; r < 8; r++) { int i = o + 64 * r; dst[sw(i)] = v[r]; }
    __syncthreads();
}

// Final radix-4 pass (NSv=512): RESULT IN REGISTERS, v[m] <-> position t+256m.
template <bool INV>
__device__ __forceinline__ void pass4_regs(const c64* src, const c64* tw, int t, c64 v[8]) {
    const c64 CI1 = INV ? PKc(-1.f, 1.f) : PKc(1.f, -1.f);
    const c64 CI2 = INV ? PKc(1.f, -1.f) : PKc(-1.f, 1.f);
    #pragma unroll
    for (int b = 0; b < 2; b++) {
        int j = t + 256 * b;
        int mr = gmask(j >> 4);
        c64 v0 = src[j ^ mr];
        c64 v1 = src[(j + 512) ^ mr];
        c64 v2 = src[(j + 1024) ^ mr];
        c64 v3 = src[(j + 1536) ^ mr];
        c64 w1 = tw[j];
        c64 w2 = cmulc(w1, w1), w3 = cmulc(w2, w1);
        v1 = capply<INV>(v1, w1);
        v2 = capply<INV>(v2, w2);
        v3 = capply<INV>(v3, w3);
        c64 aa = padd(v0, v2), bb = psub(v0, v2);
        c64 cc = padd(v1, v3), dd = psub(v1, v3);
        c64 ds = pswap(dd);
        v[b + 0] = padd(aa, cc);       v[b + 4] = psub(aa, cc);
        v[b + 2] = pfma(ds, CI1, bb);  v[b + 6] = pfma(ds, CI2, bb);
    }
}

// Full FFT on ping-pong pair (P, Q): input/output in registers (canonical
// layout v[m] <-> position t+256m). Next call must swap P and Q.
template <bool INV, bool HALF>
__device__ __forceinline__ void fft2048(c64* P, c64* Q, const c64* tw,
                                        const c64* ptw2, const c64* ptw3,
                                        int t, c64 v[8]) {
    pass1<INV, HALF>(P, v, t);
    pass2<INV>(P, Q, ptw2, t);
    pass3<INV>(Q, P, ptw3, t);
    pass4_regs<INV>(P, tw, t, v);
}

// ---------------------------------------------------------------------------
// Block reduction (256 threads)
// ---------------------------------------------------------------------------
__device__ __forceinline__ float block_reduce(float v, float* red) {
    int tid = threadIdx.x;
    #pragma unroll
    for (int o = 16; o > 0; o >>= 1) v += __shfl_xor_sync(0xffffffffu, v, o);
    if ((tid & 31) == 0) red[tid >> 5] = v;
    __syncthreads();
    if (tid < 32) {
        float r = (tid < TPB / 32) ? red[tid] : 0.f;
        #pragma unroll
        for (int o = 4; o > 0; o >>= 1) r += __shfl_xor_sync(0xffffffffu, r, o);
        if (tid == 0) red[32] = r;
    }
    __syncthreads();
    float r = red[32];
    __syncthreads();
    return r;
}

// ---------------------------------------------------------------------------
// K0: normalize each signal + forward FFT -> g_Y.  grid = 128
// ---------------------------------------------------------------------------
__global__ void __launch_bounds__(TPB) k0_normfft(const float* __restrict__ x) {
    __shared__ c64 A[NN], B[NN];
    __shared__ c64 tw[512];
    __shared__ c64 ptw2[64];
    __shared__ c64 ptw3[448];
    __shared__ float red[33];
    int b = blockIdx.x, t = threadIdx.x;
    const float* y = x + (size_t)b * NN;

    fill_tables(tw, ptw2, ptw3, t);

    float s = 0.f;
    #pragma unroll
    for (int i = t; i < NN; i += TPB) s += y[i];
    float mean = block_reduce(s, red) * (1.0f / NN);

    float vv = 0.f;
    #pragma unroll
    for (int i = t; i < NN; i += TPB) { float d = y[i] - mean; vv += d * d; }
    float istd = rsqrtf(block_reduce(vv, red) * (1.0f / NN));

    c64 v[8];
    #pragma unroll
    for (int m = 0; m < 8; m++) {
        int i = t + 256 * m;
        v[m] = PKc((y[i] - mean) * istd, 0.f);
    }
    fft2048<false, false>(A, B, tw, ptw2, ptw3, t, v);

    c64* out = g_Y + (size_t)b * NN;
    #pragma unroll
    for (int m = 0; m < 8; m++) out[t + 256 * m] = v[m];
}

// ---------------------------------------------------------------------------
// K1: per (pair, scale) full chain; FFT junctions chained in registers;
// ping-pong smem; fp16 stash keeps block smem at 48 KB (occupancy 4).
// grid = 5184
// ---------------------------------------------------------------------------
__global__ void __launch_bounds__(TPB, 4) k1_scale() {
    __shared__ c64 A[NN], B[NN];          // 32 KB ping-pong
    __shared__ __half2 X[NN];             // 8 KB stash: W1, then C (same-thread)
    __shared__ c64 tw[512];
    __shared__ c64 ptw2[64];
    __shared__ c64 ptw3[448];
    int blk = blockIdx.x;
    int pair = blk / NSC;
    int js = blk - pair * NSC;
    int t = threadIdx.x;

    fill_tables(tw, ptw2, ptw3, t);

    float sc  = S0F * exp2f(0.125f * (float)js);
    float nrm = sqrtf(TWOPI_F * sc * 10.0f) * INV_PI4;
    const c64* Y1 = g_Y + (size_t)pair * 2 * NN;
    const c64* Y2 = Y1 + NN;

    c64 v[8];

    // Morlet filter values for this thread's 4 low-half bins (reused for both CWTs)
    float hh[4];
    #pragma unroll
    for (int m = 0; m < 4; m++) {
        int i = t + 256 * m;
        float tt = sc * (WFAC * (float)i) - 6.0f;
        hh[m] = (i >= 1) ? nrm * __expf(-0.5f * tt * tt) : 0.f;
    }

    // ---- FFT1 (A-start): W1 = unscaled ifft(Y1*H) -> stash to X (fp16) ----
    #pragma unroll
    for (int m = 0; m < 4; m++) v[m] = pmul(Y1[t + 256 * m], PKc(hh[m], hh[m]));
    fft2048<true, true>(A, B, tw, ptw2, ptw3, t, v);
    #pragma unroll
    for (int m = 0; m < 8; m++) {
        float xx, yy; UPKc(v[m], xx, yy);
        X[t + 256 * m] = __floats2half2_rn(xx, yy);       // same-thread stash
    }

    // ---- FFT2 (B-start): W2 -> registers ----
    #pragma unroll
    for (int m = 0; m < 4; m++) v[m] = pmul(Y2[t + 256 * m], PKc(hh[m], hh[m]));
    fft2048<true, true>(B, A, tw, ptw2, ptw3, t, v);      // v = W2

    // ---- pointwise: pv = (|W1|^2 + i|W2|^2)*scf -> regs;  C = W1*conj(W2)*scf -> X
    const float scf = (LAMB / sc) * (1.0f / ((float)NN * (float)NN));
    #pragma unroll
    for (int m = 0; m < 8; m++) {
        float2 w1 = __half22float2(X[t + 256 * m]);       // same-thread reload
        float w2x, w2y;
        UPKc(v[m], w2x, w2y);
        X[t + 256 * m] = __floats2half2_rn((w1.x * w2x + w1.y * w2y) * scf,
                                           (w1.y * w2x - w1.x * w2y) * scf);
        v[m] = PKc((w1.x * w1.x + w1.y * w1.y) * scf,
                   (w2x * w2x + w2y * w2y) * scf);
    }

    // ---- FFT3 (A-start): forward fft of packed P ----
    fft2048<false, false>(A, B, tw, ptw2, ptw3, t, v);

    // ---- Gaussian smoother in registers ----
    float sd = sc * 10.0f;
    float a2 = sd * sd;
    const float invN = 1.0f / (float)NN;
    #pragma unroll
    for (int m = 0; m < 8; m++) {
        int i = t + 256 * m;
        int f = (i < 1024) ? i : (NN - i);
        float k = KFAC * (float)f;
        float g = __expf(-0.5f * a2 * k * k) * invN;
        v[m] = pmul(v[m], PKc(g, g));
    }

    // ---- FFT4 (B-start): inverse fft, write (T1,T2) as fp16 pairs ----
    size_t base = ((size_t)pair * NSC + js) * NN;
    fft2048<true, false>(B, A, tw, ptw2, ptw3, t, v);
    {
        __half2* Tp = g_Tp + base;
        #pragma unroll
        for (int m = 0; m < 8; m++) {
            float xx, yy; UPKc(v[m], xx, yy);
            Tp[t + 256 * m] = __floats2half2_rn(xx, yy);
        }
    }

    // ---- FFT5 (A-start): forward fft of C (same-thread reload from X) ----
    #pragma unroll
    for (int m = 0; m < 8; m++) {
        float2 c = __half22float2(X[t + 256 * m]);
        v[m] = PKc(c.x, c.y);
    }
    fft2048<false, false>(A, B, tw, ptw2, ptw3, t, v);

    // ---- Gaussian + FFT6 (B-start): inverse fft, write T12 as fp16 pairs ----
    #pragma unroll
    for (int m = 0; m < 8; m++) {
        int i = t + 256 * m;
        int f = (i < 1024) ? i : (NN - i);
        float k = KFAC * (float)f;
        float g = __expf(-0.5f * a2 * k * k) * invN;
        v[m] = pmul(v[m], PKc(g, g));
    }
    fft2048<true, false>(B, A, tw, ptw2, ptw3, t, v);
    {
        __half2* Tc = g_Tc + base;
        #pragma unroll
        for (int m = 0; m < 8; m++) {
            float xx, yy; UPKc(v[m], xx, yy);
            Tc[t + 256 * m] = __floats2half2_rn(xx, yy);
        }
    }
}

// ---------------------------------------------------------------------------
// K2: scale smoothing (10-tap, half ends) + coherence + sum over scales.
// 1/9 window norm and LAMB cancel in the ratio. grid = 64*64
// ---------------------------------------------------------------------------
__global__ void __launch_bounds__(TPB) k2_coh() {
    __shared__ float s1[NSC * 32], s2[NSC * 32], cr[NSC * 32], ci[NSC * 32];
    __shared__ float scoh[32];
    int blk = blockIdx.x;
    int pair = blk >> 6;
    int t0 = (blk & 63) * 32;
    int tid = threadIdx.x;

    size_t base = (size_t)pair * NSC * NN + t0;
    for (int idx = tid; idx < NSC * 32; idx += TPB) {
        int row = idx >> 5, col = idx & 31;
        size_t g = base + (size_t)row * NN + col;
        float2 p = __half22float2(g_Tp[g]);
        float2 c = __half22float2(g_Tc[g]);
        s1[idx] = p.x;
        s2[idx] = p.y;
        cr[idx] = c.x;
        ci[idx] = c.y;
    }
    if (tid < 32) scoh[tid] = 0.f;
    __syncthreads();

    int tl = tid & 31, jg = tid >> 5;
    float acc = 0.f;
    for (int j = jg; j < NSC; j += 8) {
        float a = 0.f, b = 0.f, c = 0.f, d = 0.f;
        #pragma unroll
        for (int k = 0; k < 10; k++) {
            int r = j + 4 - k;
            if (r >= 0 && r < NSC) {
                float w = (k == 0 || k == 9) ? 0.5f : 1.0f;
                int ix = r * 32 + tl;
                a += w * s1[ix];
                b += w * s2[ix];
                c += w * cr[ix];
                d += w * ci[ix];
            }
        }
        acc += (c * c + d * d) / (a * b);
    }
    atomicAdd(&scoh[tl], acc);
    __syncthreads();
    if (tid < 32) g_coh[(size_t)pair * NN + t0 + tid] = scoh[tid];
}

// ---------------------------------------------------------------------------
// K3: sliding-window sum (window 94) -> out [64, 1955]. grid = 64*8 tiles
// ---------------------------------------------------------------------------
__global__ void __launch_bounds__(TPB) k3_window(float* __restrict__ out) {
    __shared__ float c[TPB + WSZ];
    int pair = blockIdx.x >> 3;
    int t0 = (blockIdx.x & 7) * TPB;
    int tid = threadIdx.x;
    for (int i = tid; i < TPB + WSZ; i += TPB) {
        int g = t0 + i;
        c[i] = (g < NN) ? g_coh[(size_t)pair * NN + g] : 0.f;
    }
    __syncthreads();
    int t = t0 + tid;
    if (t < NOUT) {
        float s = 0.f;
        #pragma unroll
        for (int k = 0; k < WSZ; k++) s += c[tid + k];
        out[(size_t)pair * NOUT + t] = s;
    }
}

// ---------------------------------------------------------------------------
// Entry point
// ---------------------------------------------------------------------------
extern "C" void kernel_launch(void* const* d_in, const int* in_sizes, int n_in,
                              void* d_out, int out_size) {
    (void)in_sizes; (void)n_in; (void)out_size;
    const float* x = (const float*)d_in[0];
    float* out = (float*)d_out;

    k0_normfft<<<NB * 2, TPB>>>(x);
    k1_scale<<<NB * NSC, TPB>>>();
    k2_coh<<<NB * 64, TPB>>>();
    k3_window<<<NB * 8, TPB>>>(out);
}

// round 15
// speedup vs baseline: 1.1494x; 1.1494x over previous
#include <cuda_runtime.h>
#include <cuda_fp16.h>

// ---------------------------------------------------------------------------
// Problem constants
// ---------------------------------------------------------------------------
#define NN     2048
#define NSC    81
#define NB     64
#define TPB    256
#define WSZ    94
#define NOUT   (NN - WSZ + 1)  // 1955

#define S0F        0.1936026618f            // 2*dt*(w0+sqrt(2+w0^2))/(4*pi)
#define WFAC       0.030679615757712823f    // 2*pi / (2048*0.1)
#define KFAC       0.0030679615757712823f   // 2*pi / 2048
#define TWOPI_F    6.283185307179586f
#define INV_PI4    0.7511255444649425f      // pi^(-1/4)
#define RSQ2       0.70710678118654752f
#define LAMB       16.0f                    // fp16 range centering; cancels in ratio

// ---------------------------------------------------------------------------
// Packed complex type: one 64-bit reg pair holding (re, im) as f32x2
// ---------------------------------------------------------------------------
typedef unsigned long long c64;

__device__ __forceinline__ c64 PKc(float x, float y) {
    c64 r; asm("mov.b64 %0, {%1,%2};" : "=l"(r) : "f"(x), "f"(y)); return r;
}
__device__ __forceinline__ void UPKc(c64 v, float& x, float& y) {
    asm("mov.b64 {%0,%1}, %2;" : "=f"(x), "=f"(y) : "l"(v));
}
__device__ __forceinline__ c64 padd(c64 a, c64 b) {
    c64 r; asm("add.rn.f32x2 %0, %1, %2;" : "=l"(r) : "l"(a), "l"(b)); return r;
}
__device__ __forceinline__ c64 pmul(c64 a, c64 b) {
    c64 r; asm("mul.rn.f32x2 %0, %1, %2;" : "=l"(r) : "l"(a), "l"(b)); return r;
}
__device__ __forceinline__ c64 pfma(c64 a, c64 b, c64 c) {
    c64 r; asm("fma.rn.f32x2 %0, %1, %2, %3;" : "=l"(r) : "l"(a), "l"(b), "l"(c)); return r;
}
__device__ __forceinline__ c64 psub(c64 a, c64 b) { return pfma(b, PKc(-1.f, -1.f), a); }
__device__ __forceinline__ c64 pswap(c64 v) { float x, y; UPKc(v, x, y); return PKc(y, x); }

// a*b (4 fp instrs)
__device__ __forceinline__ c64 cmulc(c64 a, c64 b) {
    float ax, ay, bx, by; UPKc(a, ax, ay); UPKc(b, bx, by);
    return PKc(fmaf(ax, bx, -ay * by), fmaf(ax, by, ay * bx));
}
// a*conj(b) (4 fp instrs) — inverse twiddles without negation
__device__ __forceinline__ c64 cmulcj(c64 a, c64 b) {
    float ax, ay, bx, by; UPKc(a, ax, ay); UPKc(b, bx, by);
    return PKc(fmaf(ax, bx, ay * by), fmaf(ay, bx, -ax * by));
}
template <bool INV>
__device__ __forceinline__ c64 capply(c64 a, c64 w) {
    return INV ? cmulcj(a, w) : cmulc(a, w);
}

// ---------------------------------------------------------------------------
// Scratch (device globals; no allocation anywhere)
// ---------------------------------------------------------------------------
static __device__ c64     g_Y [NB * 2 * NN];
static __device__ __half2 g_Tp[(size_t)NB * NSC * NN];  // (T1, T2) fp16 pair
static __device__ __half2 g_Tc[(size_t)NB * NSC * NN];  // (T12.re, T12.im) fp16 pair
static __device__ float   g_coh[NB * NN];

// ---------------------------------------------------------------------------
// Data-buffer bank swizzle (conflict-free for all FFT patterns below)
// ---------------------------------------------------------------------------
__device__ __forceinline__ int gmask(int h) { return (h & 7) ^ ((h & 4) << 1); }
__device__ __forceinline__ int sw(int i)    { return i ^ gmask(i >> 4); }

// ---------------------------------------------------------------------------
// Twiddle tables (forward sign; INV uses a*conj(w)):
//   tw[k]           = exp(-i*pi*k/1024), k in [0,512)   (pass4 w1, linear reads)
//   ptw2[m*8+p]     = exp(-i*pi*m*p/32),  m in [0,8), p in [0,8)
//   ptw3[(m-1)*64+p]= exp(-i*pi*m*p/256), m in [1,8), p in [0,64)
// ---------------------------------------------------------------------------
__device__ __forceinline__ void fill_tables(c64* tw, c64* ptw2, c64* ptw3, int t) {
    #pragma unroll
    for (int k = t; k < 512; k += TPB) {
        float s, c;
        sincospif(-(float)k * (1.0f / 1024.0f), &s, &c);
        tw[k] = PKc(c, s);
    }
    if (t < 64) {
        int m = t >> 3, p = t & 7;
        float s, c;
        sincospif(-(float)(m * p) * (1.0f / 32.0f), &s, &c);
        ptw2[t] = PKc(c, s);
    }
    #pragma unroll
    for (int k = t; k < 448; k += TPB) {
        int m = 1 + (k >> 6), p = k & 63;
        float s, c;
        sincospif(-(float)(m * p) * (1.0f / 256.0f), &s, &c);
        ptw3[k] = PKc(c, s);
    }
}

// ---------------------------------------------------------------------------
// Packed radix-8 butterflies
// ---------------------------------------------------------------------------
template <bool INV>
__device__ __forceinline__ void bf8_tail(c64 E0, c64 E1, c64 E2, c64 E3,
                                         c64 O0, c64 O1, c64 O2, c64 O3,
                                         c64 v[8]) {
    const c64 CI1 = INV ? PKc(-1.f, 1.f) : PKc(1.f, -1.f);
    const c64 CI2 = INV ? PKc(1.f, -1.f) : PKc(-1.f, 1.f);
    const c64 PIM = PKc(-1.f, 1.f);
    c64 q1 = pfma(pswap(O1), PIM, O1);
    c64 q3 = pfma(pswap(O3), PIM, O3);
    c64 W1 = INV ? pmul(q1, PKc(RSQ2, RSQ2))
                 : pmul(pswap(q1), PKc(RSQ2, -RSQ2));
    c64 W3 = INV ? pmul(pswap(q3), PKc(-RSQ2, RSQ2))
                 : pmul(q3, PKc(-RSQ2, -RSQ2));
    c64 O2s = pswap(O2);
    v[0] = padd(E0, O0);        v[4] = psub(E0, O0);
    v[1] = padd(E1, W1);        v[5] = psub(E1, W1);
    v[2] = pfma(O2s, CI1, E2);  v[6] = pfma(O2s, CI2, E2);
    v[3] = padd(E3, W3);        v[7] = psub(E3, W3);
}

template <bool INV>
__device__ __forceinline__ void bf8(c64 v[8]) {
    const c64 CI1 = INV ? PKc(-1.f, 1.f) : PKc(1.f, -1.f);
    const c64 CI2 = INV ? PKc(1.f, -1.f) : PKc(-1.f, 1.f);
    c64 e0 = padd(v[0], v[4]), e1 = psub(v[0], v[4]);
    c64 e2 = padd(v[2], v[6]), e3 = psub(v[2], v[6]);
    c64 e3s = pswap(e3);
    c64 E0 = padd(e0, e2), E2 = psub(e0, e2);
    c64 E1 = pfma(e3s, CI1, e1), E3 = pfma(e3s, CI2, e1);
    c64 o0 = padd(v[1], v[5]), o1 = psub(v[1], v[5]);
    c64 o2 = padd(v[3], v[7]), o3 = psub(v[3], v[7]);
    c64 o3s = pswap(o3);
    c64 O0 = padd(o0, o2), O2 = psub(o0, o2);
    c64 O1 = pfma(o3s, CI1, o1), O3 = pfma(o3s, CI2, o1);
    bf8_tail<INV>(E0, E1, E2, E3, O0, O1, O2, O3, v);
}

// Half-input butterfly: v[0..3] valid, v[4..7] == 0
template <bool INV>
__device__ __forceinline__ void bf8h(c64 v[8]) {
    const c64 CI1 = INV ? PKc(-1.f, 1.f) : PKc(1.f, -1.f);
    const c64 CI2 = INV ? PKc(1.f, -1.f) : PKc(-1.f, 1.f);
    c64 a0 = v[0], a1 = v[2], b0 = v[1], b1 = v[3];
    c64 a1s = pswap(a1);
    c64 E0 = padd(a0, a1), E2 = psub(a0, a1);
    c64 E1 = pfma(a1s, CI1, a0), E3 = pfma(a1s, CI2, a0);
    c64 b1s = pswap(b1);
    c64 O0 = padd(b0, b1), O2 = psub(b0, b1);
    c64 O1 = pfma(b1s, CI1, b0), O3 = pfma(b1s, CI2, b0);
    bf8_tail<INV>(E0, E1, E2, E3, O0, O1, O2, O3, v);
}

// Two-input butterfly: only v[0] and v[7] valid (narrow-band smoother spectra).
// out[r] = v0 + e^{±i*pi*r/4} * v7   (forward: +, inverse: −)
template <bool INV>
__device__ __forceinline__ void bf8_07(c64 v[8]) {
    const c64 SGN = INV ? PKc(1.f, -1.f) : PKc(-1.f, 1.f);
    c64 a = v[0], b = v[7];
    c64 q   = pfma(pswap(b), SGN, b);          // fwd: (bx-by, bx+by)
    c64 e1  = pmul(q, PKc(RSQ2, RSQ2));        // e^{±i pi/4} b
    c64 ib  = pmul(pswap(b), SGN);             // ±i b
    c64 ie1 = pmul(pswap(e1), SGN);            // e^{±i 3pi/4} b
    v[0] = padd(a, b);   v[1] = padd(a, e1);
    v[2] = padd(a, ib);  v[3] = padd(a, ie1);
    v[4] = psub(a, b);   v[5] = psub(a, e1);
    v[6] = psub(a, ib);  v[7] = psub(a, ie1);
}

// ---------------------------------------------------------------------------
// Stockham passes, N = 2048 = 8*8*8*4, 256 threads, in-place buffer A.
// Thread t's register set v[m] maps to logical positions t + 256*m at FFT
// boundaries — pass4_regs feeds pass1 / elementwise ops directly.
// mode: 0=full bf8, 1=half (bins<1024), 2=broadcast (only v[0], bins<256),
//       3=v0+v7 (narrow-band smoother). Block-uniform.
// ---------------------------------------------------------------------------
template <bool INV>
__device__ __forceinline__ void pass1(c64* A, c64 v[8], int t, int mode) {
    __syncthreads();           // prior readers of A are done
    if (mode == 0)      bf8<INV>(v);
    else if (mode == 1) bf8h<INV>(v);
    else if (mode == 2) {
        #pragma unroll
        for (int r = 1; r < 8; r++) v[r] = v[0];   // DFT of (x,0,...,0)
    } else              bf8_07<INV>(v);
    int mw = gmask(t >> 1);
    int b8 = 8 * t;
    #pragma unroll
    for (int r = 0; r < 8; r++) A[(b8 + r) ^ mw] = v[r];
    __syncthreads();
}

template <bool INV>
__device__ __forceinline__ void pass2(c64* A, const c64* ptw2, int t) {
    c64 v[8];
    int mr = gmask(t >> 4);
    #pragma unroll
    for (int m = 0; m < 8; m++) v[m] = A[(t + 256 * m) ^ mr];
    int p = t & 7;
    #pragma unroll
    for (int m = 1; m < 8; m++) v[m] = capply<INV>(v[m], ptw2[m * 8 + p]);
    bf8<INV>(v);               // register work hoisted before the barrier
    __syncthreads();
    int o = (t >> 3) * 64 + p;
    #pragma unroll
    for (int r = 0; r < 8; r++) { int i = o + 8 * r; A[sw(i)] = v[r]; }
    __syncthreads();
}

template <bool INV>
__device__ __forceinline__ void pass3(c64* A, const c64* ptw3, int t) {
    c64 v[8];
    int mr = gmask(t >> 4);
    #pragma unroll
    for (int m = 0; m < 8; m++) v[m] = A[(t + 256 * m) ^ mr];
    int p = t & 63;
    #pragma unroll
    for (int m = 1; m < 8; m++) v[m] = capply<INV>(v[m], ptw3[(m - 1) * 64 + p]);
    bf8<INV>(v);
    __syncthreads();
    int o = (t >> 6) * 512 + p;
    #pragma unroll
    for (int r = 0; r < 8; r++) { int i = o + 64 * r; A[sw(i)] = v[r]; }
    __syncthreads();
}

// Final radix-4 pass (NSv=512): RESULT IN REGISTERS, v[m] <-> position t+256m.
// No sync — the next pass1's leading sync protects A.
template <bool INV>
__device__ __forceinline__ void pass4_regs(const c64* A, const c64* tw, int t, c64 v[8]) {
    const c64 CI1 = INV ? PKc(-1.f, 1.f) : PKc(1.f, -1.f);
    const c64 CI2 = INV ? PKc(1.f, -1.f) : PKc(-1.f, 1.f);
    #pragma unroll
    for (int b = 0; b < 2; b++) {
        int j = t + 256 * b;
        int mr = gmask(j >> 4);
        c64 v0 = A[j ^ mr];
        c64 v1 = A[(j + 512) ^ mr];
        c64 v2 = A[(j + 1024) ^ mr];
        c64 v3 = A[(j + 1536) ^ mr];
        c64 w1 = tw[j];
        c64 w2 = cmulc(w1, w1), w3 = cmulc(w2, w1);
        v1 = capply<INV>(v1, w1);
        v2 = capply<INV>(v2, w2);
        v3 = capply<INV>(v3, w3);
        c64 aa = padd(v0, v2), bb = psub(v0, v2);
        c64 cc = padd(v1, v3), dd = psub(v1, v3);
        c64 ds = pswap(dd);
        v[b + 0] = padd(aa, cc);       v[b + 4] = psub(aa, cc);
        v[b + 2] = pfma(ds, CI1, bb);  v[b + 6] = pfma(ds, CI2, bb);
    }
}

// ---------------------------------------------------------------------------
// Block reduction (256 threads)
// ---------------------------------------------------------------------------
__device__ __forceinline__ float block_reduce(float v, float* red) {
    int tid = threadIdx.x;
    #pragma unroll
    for (int o = 16; o > 0; o >>= 1) v += __shfl_xor_sync(0xffffffffu, v, o);
    if ((tid & 31) == 0) red[tid >> 5] = v;
    __syncthreads();
    if (tid < 32) {
        float r = (tid < TPB / 32) ? red[tid] : 0.f;
        #pragma unroll
        for (int o = 4; o > 0; o >>= 1) r += __shfl_xor_sync(0xffffffffu, r, o);
        if (tid == 0) red[32] = r;
    }
    __syncthreads();
    float r = red[32];
    __syncthreads();
    return r;
}

// ---------------------------------------------------------------------------
// K0: normalize each signal + forward FFT -> g_Y.  grid = 128
// ---------------------------------------------------------------------------
__global__ void __launch_bounds__(TPB) k0_normfft(const float* __restrict__ x) {
    __shared__ c64 A[NN];
    __shared__ c64 tw[512];
    __shared__ c64 ptw2[64];
    __shared__ c64 ptw3[448];
    __shared__ float red[33];
    int b = blockIdx.x, t = threadIdx.x;
    const float* y = x + (size_t)b * NN;

    fill_tables(tw, ptw2, ptw3, t);

    float s = 0.f;
    #pragma unroll
    for (int i = t; i < NN; i += TPB) s += y[i];
    float mean = block_reduce(s, red) * (1.0f / NN);

    float vv = 0.f;
    #pragma unroll
    for (int i = t; i < NN; i += TPB) { float d = y[i] - mean; vv += d * d; }
    float istd = rsqrtf(block_reduce(vv, red) * (1.0f / NN));

    c64 v[8];
    #pragma unroll
    for (int m = 0; m < 8; m++) {
        int i = t + 256 * m;
        v[m] = PKc((y[i] - mean) * istd, 0.f);
    }
    pass1<false>(A, v, t, 0);
    pass2<false>(A, ptw2, t);
    pass3<false>(A, ptw3, t);
    pass4_regs<false>(A, tw, t, v);

    c64* out = g_Y + (size_t)b * NN;
    #pragma unroll
    for (int m = 0; m < 8; m++) out[t + 256 * m] = v[m];
}

// ---------------------------------------------------------------------------
// K1: per (pair, scale) full chain; single in-place A buffer (proven layout);
// fp16 stash; scale-dependent sparse first passes. grid = 5184
// ---------------------------------------------------------------------------
__global__ void __launch_bounds__(TPB, 4) k1_scale() {
    __shared__ c64 A[NN];                 // 16 KB in-place FFT buffer
    __shared__ __half2 X[NN];             // 8 KB stash: W1, then C (same-thread)
    __shared__ c64 tw[512];
    __shared__ c64 ptw2[64];
    __shared__ c64 ptw3[448];
    int blk = blockIdx.x;
    int pair = blk / NSC;
    int js = blk - pair * NSC;
    int t = threadIdx.x;

    fill_tables(tw, ptw2, ptw3, t);

    float sc  = S0F * exp2f(0.125f * (float)js);
    float nrm = sqrtf(TWOPI_F * sc * 10.0f) * INV_PI4;
    const c64* Y1 = g_Y + (size_t)pair * 2 * NN;
    const c64* Y2 = Y1 + NN;

    // Sparsity modes (block-uniform):
    //  cwt_mode==2: Morlet support entirely in bins < 256  (js >= ~25)
    //  sm_mode ==3: Gaussian smoother support min(f,2048-f) < 256 (js >= ~17)
    float iW  = sc * WFAC;                // filter arg slope per bin
    float gsl = sc * 10.0f * KFAC;        // smoother arg slope per bin
    int cwt_mode = (12.2f < 255.5f * iW) ? 2 : 1;
    int sm_mode  = (6.1f  < 255.5f * gsl) ? 3 : 0;

    c64 v[8];

    // Morlet filter values for this thread's low-half bins
    float hh[4];
    if (cwt_mode == 2) {
        float tt = iW * (float)t - 6.0f;
        hh[0] = (t >= 1) ? nrm * __expf(-0.5f * tt * tt) : 0.f;
    } else {
        #pragma unroll
        for (int m = 0; m < 4; m++) {
            int i = t + 256 * m;
            float tt = iW * (float)i - 6.0f;
            hh[m] = (i >= 1) ? nrm * __expf(-0.5f * tt * tt) : 0.f;
        }
    }

    // ---- FFT1: W1 = unscaled ifft(Y1*H) -> stash to X (fp16) ----
    if (cwt_mode == 2) {
        v[0] = pmul(Y1[t], PKc(hh[0], hh[0]));
    } else {
        #pragma unroll
        for (int m = 0; m < 4; m++) v[m] = pmul(Y1[t + 256 * m], PKc(hh[m], hh[m]));
    }
    pass1<true>(A, v, t, cwt_mode);
    pass2<true>(A, ptw2, t);
    pass3<true>(A, ptw3, t);
    pass4_regs<true>(A, tw, t, v);
    #pragma unroll
    for (int m = 0; m < 8; m++) {
        float xx, yy; UPKc(v[m], xx, yy);
        X[t + 256 * m] = __floats2half2_rn(xx, yy);       // same-thread stash
    }

    // ---- FFT2: W2 -> registers ----
    if (cwt_mode == 2) {
        v[0] = pmul(Y2[t], PKc(hh[0], hh[0]));
    } else {
        #pragma unroll
        for (int m = 0; m < 4; m++) v[m] = pmul(Y2[t + 256 * m], PKc(hh[m], hh[m]));
    }
    pass1<true>(A, v, t, cwt_mode);
    pass2<true>(A, ptw2, t);
    pass3<true>(A, ptw3, t);
    pass4_regs<true>(A, tw, t, v);                        // v = W2

    // ---- pointwise: pv = (|W1|^2 + i|W2|^2)*scf -> regs;  C = W1*conj(W2)*scf -> X
    const float scf = (LAMB / sc) * (1.0f / ((float)NN * (float)NN));
    #pragma unroll
    for (int m = 0; m < 8; m++) {
        float2 w1 = __half22float2(X[t + 256 * m]);       // same-thread reload
        float w2x, w2y;
        UPKc(v[m], w2x, w2y);
        X[t + 256 * m] = __floats2half2_rn((w1.x * w2x + w1.y * w2y) * scf,
                                           (w1.y * w2x - w1.x * w2y) * scf);
        v[m] = PKc((w1.x * w1.x + w1.y * w1.y) * scf,
                   (w2x * w2x + w2y * w2y) * scf);
    }

    // ---- FFT3: forward fft of packed P (time-domain input: full) ----
    pass1<false>(A, v, t, 0);
    pass2<false>(A, ptw2, t);
    pass3<false>(A, ptw3, t);
    pass4_regs<false>(A, tw, t, v);

    // ---- Gaussian smoother in registers ----
    const float invN = 1.0f / (float)NN;
    if (sm_mode == 3) {
        float f0 = gsl * (float)t;
        float g0 = __expf(-0.5f * f0 * f0) * invN;
        float f7 = gsl * (float)(256 - t);
        float g7 = __expf(-0.5f * f7 * f7) * invN;
        v[0] = pmul(v[0], PKc(g0, g0));
        v[7] = pmul(v[7], PKc(g7, g7));
    } else {
        #pragma unroll
        for (int m = 0; m < 8; m++) {
            int i = t + 256 * m;
            int f = (i < 1024) ? i : (NN - i);
            float a = gsl * (float)f;
            float g = __expf(-0.5f * a * a) * invN;
            v[m] = pmul(v[m], PKc(g, g));
        }
    }

    // ---- FFT4: inverse fft, write (T1,T2) as fp16 pairs ----
    size_t base = ((size_t)pair * NSC + js) * NN;
    pass1<true>(A, v, t, sm_mode);
    pass2<true>(A, ptw2, t);
    pass3<true>(A, ptw3, t);
    pass4_regs<true>(A, tw, t, v);
    {
        __half2* Tp = g_Tp + base;
        #pragma unroll
        for (int m = 0; m < 8; m++) {
            float xx, yy; UPKc(v[m], xx, yy);
            Tp[t + 256 * m] = __floats2half2_rn(xx, yy);
        }
    }

    // ---- FFT5: forward fft of C (same-thread reload from X; time-domain: full) ----
    #pragma unroll
    for (int m = 0; m < 8; m++) {
        float2 c = __half22float2(X[t + 256 * m]);
        v[m] = PKc(c.x, c.y);
    }
    pass1<false>(A, v, t, 0);
    pass2<false>(A, ptw2, t);
    pass3<false>(A, ptw3, t);
    pass4_regs<false>(A, tw, t, v);

    // ---- Gaussian + FFT6: inverse fft, write T12 as fp16 pairs ----
    if (sm_mode == 3) {
        float f0 = gsl * (float)t;
        float g0 = __expf(-0.5f * f0 * f0) * invN;
        float f7 = gsl * (float)(256 - t);
        float g7 = __expf(-0.5f * f7 * f7) * invN;
        v[0] = pmul(v[0], PKc(g0, g0));
        v[7] = pmul(v[7], PKc(g7, g7));
    } else {
        #pragma unroll
        for (int m = 0; m < 8; m++) {
            int i = t + 256 * m;
            int f = (i < 1024) ? i : (NN - i);
            float a = gsl * (float)f;
            float g = __expf(-0.5f * a * a) * invN;
            v[m] = pmul(v[m], PKc(g, g));
        }
    }
    pass1<true>(A, v, t, sm_mode);
    pass2<true>(A, ptw2, t);
    pass3<true>(A, ptw3, t);
    pass4_regs<true>(A, tw, t, v);
    {
        __half2* Tc = g_Tc + base;
        #pragma unroll
        for (int m = 0; m < 8; m++) {
            float xx, yy; UPKc(v[m], xx, yy);
            Tc[t + 256 * m] = __floats2half2_rn(xx, yy);
        }
    }
}

// ---------------------------------------------------------------------------
// K2: scale smoothing (10-tap, half ends) + coherence + sum over scales.
// 1/9 window norm and LAMB cancel in the ratio. grid = 64*64
// ---------------------------------------------------------------------------
__global__ void __launch_bounds__(TPB) k2_coh() {
    __shared__ float s1[NSC * 32], s2[NSC * 32], cr[NSC * 32], ci[NSC * 32];
    __shared__ float scoh[32];
    int blk = blockIdx.x;
    int pair = blk >> 6;
    int t0 = (blk & 63) * 32;
    int tid = threadIdx.x;

    size_t base = (size_t)pair * NSC * NN + t0;
    for (int idx = tid; idx < NSC * 32; idx += TPB) {
        int row = idx >> 5, col = idx & 31;
        size_t g = base + (size_t)row * NN + col;
        float2 p = __half22float2(g_Tp[g]);
        float2 c = __half22float2(g_Tc[g]);
        s1[idx] = p.x;
        s2[idx] = p.y;
        cr[idx] = c.x;
        ci[idx] = c.y;
    }
    if (tid < 32) scoh[tid] = 0.f;
    __syncthreads();

    int tl = tid & 31, jg = tid >> 5;
    float acc = 0.f;
    for (int j = jg; j < NSC; j += 8) {
        float a = 0.f, b = 0.f, c = 0.f, d = 0.f;
        #pragma unroll
        for (int k = 0; k < 10; k++) {
            int r = j + 4 - k;
            if (r >= 0 && r < NSC) {
                float w = (k == 0 || k == 9) ? 0.5f : 1.0f;
                int ix = r * 32 + tl;
                a += w * s1[ix];
                b += w * s2[ix];
                c += w * cr[ix];
                d += w * ci[ix];
            }
        }
        acc += (c * c + d * d) / (a * b);
    }
    atomicAdd(&scoh[tl], acc);
    __syncthreads();
    if (tid < 32) g_coh[(size_t)pair * NN + t0 + tid] = scoh[tid];
}

// ---------------------------------------------------------------------------
// K3: sliding-window sum (window 94) -> out [64, 1955]. grid = 64*8 tiles
// ---------------------------------------------------------------------------
__global__ void __launch_bounds__(TPB) k3_window(float* __restrict__ out) {
    __shared__ float c[TPB + WSZ];
    int pair = blockIdx.x >> 3;
    int t0 = (blockIdx.x & 7) * TPB;
    int tid = threadIdx.x;
    for (int i = tid; i < TPB + WSZ; i += TPB) {
        int g = t0 + i;
        c[i] = (g < NN) ? g_coh[(size_t)pair * NN + g] : 0.f;
    }
    __syncthreads();
    int t = t0 + tid;
    if (t < NOUT) {
        float s = 0.f;
        #pragma unroll
        for (int k = 0; k < WSZ; k++) s += c[tid + k];
        out[(size_t)pair * NOUT + t] = s;
    }
}

// ---------------------------------------------------------------------------
// Entry point
// ---------------------------------------------------------------------------
extern "C" void kernel_launch(void* const* d_in, const int* in_sizes, int n_in,
                              void* d_out, int out_size) {
    (void)in_sizes; (void)n_in; (void)out_size;
    const float* x = (const float*)d_in[0];
    float* out = (float*)d_out;

    k0_normfft<<<NB * 2, TPB>>>(x);
    k1_scale<<<NB * NSC, TPB>>>();
    k2_coh<<<NB * 64, TPB>>>();
    k3_window<<<NB * 8, TPB>>>(out);
}